// round 13
// baseline (speedup 1.0000x reference)
#include <cuda_runtime.h>
#include <cuda_bf16.h>
#include <math.h>
#include <cstdint>

constexpr int Bc = 4;
constexpr int Lc = 2048;
constexpr int Dd = 1024;
constexpr int Hh = 16;
constexpr int DK = 64;
constexpr int Mtok = Bc * Lc;   // 8192

// ---------------- scratch ----------------
__device__ float g_Q[Bc * Hh * Lc * DK];   // [B,H,L,DK] (tf32 bits)
__device__ float g_K[Bc * Hh * Lc * DK];
__device__ float g_Vt[Bc * Hh * DK * Lc];  // [B,H,DK,L] (tf32 bits)
__device__ float g_att[Bc * Lc * Dd];      // [B,L,D]    (tf32 bits)
__device__ float g_conv[7340032 * 4];      // concatenated tf32 copies

// segment offsets in float4 units
constexpr int SEG_Q  = 0;
constexpr int SEG_K  = 2097152;
constexpr int SEG_V  = 4194304;
constexpr int SEG_WQ = 6291456;
constexpr int SEG_WK = 6553600;
constexpr int SEG_WV = 6815744;
constexpr int SEG_WO = 7077888;
constexpr int SEG_TOT = 7340032;

// ---------------- helpers ----------------
__device__ __forceinline__ uint32_t f2tf32(float f) {
    uint32_t r;
    asm("cvt.rna.tf32.f32 %0, %1;" : "=r"(r) : "f"(f));
    return r;
}

__device__ __forceinline__ void mma_tf32(float* d, const uint32_t* a, const uint32_t* b) {
    asm volatile(
        "mma.sync.aligned.m16n8k8.row.col.f32.tf32.tf32.f32 "
        "{%0,%1,%2,%3}, {%4,%5,%6,%7}, {%8,%9}, {%0,%1,%2,%3};\n"
        : "+f"(d[0]), "+f"(d[1]), "+f"(d[2]), "+f"(d[3])
        : "r"(a[0]), "r"(a[1]), "r"(a[2]), "r"(a[3]), "r"(b[0]), "r"(b[1]));
}

__device__ __forceinline__ void ldsm4(uint32_t* r, uint32_t addr) {
    asm volatile("ldmatrix.sync.aligned.m8n8.x4.shared.b16 {%0,%1,%2,%3}, [%4];"
                 : "=r"(r[0]), "=r"(r[1]), "=r"(r[2]), "=r"(r[3]) : "r"(addr));
}

__device__ __forceinline__ uint32_t smem_u32(const void* p) {
    uint32_t a;
    asm("{ .reg .u64 t; cvta.to.shared.u64 t, %1; cvt.u32.u64 %0, t; }" : "=r"(a) : "l"(p));
    return a;
}

#define CP16(dst, src) \
    asm volatile("cp.async.cg.shared.global [%0], [%1], 16;" :: "r"(dst), "l"(src))
#define CP_COMMIT() asm volatile("cp.async.commit_group;")
#define CP_WAIT1()  asm volatile("cp.async.wait_group 1;")

// ---------------- fused tf32 pre-convert (all 7 tensors) ----------------
struct ConvArgs {
    const float4* s0; const float4* s1; const float4* s2;
    const float4* s3; const float4* s4; const float4* s5; const float4* s6;
    float4* dst;
};

__global__ void __launch_bounds__(256) conv_all_kernel(ConvArgs a)
{
    const int g = blockIdx.x * 256 + threadIdx.x;
    constexpr int NT = SEG_TOT / 4;
    #pragma unroll
    for (int p = 0; p < 4; p++) {
        const int idx = g + p * NT;
        float4 v;
        if (idx < SEG_WQ) {
            const int seg = idx >> 21;
            const int off = idx & 2097151;
            v = (seg == 0) ? a.s0[off] : (seg == 1) ? a.s1[off] : a.s2[off];
        } else {
            const int r = idx - SEG_WQ;
            const int seg = r >> 18;
            const int off = r & 262143;
            v = (seg == 0) ? a.s3[off] : (seg == 1) ? a.s4[off]
              : (seg == 2) ? a.s5[off] : a.s6[off];
        }
        uint4 u;
        u.x = f2tf32(v.x); u.y = f2tf32(v.y); u.z = f2tf32(v.z); u.w = f2tf32(v.w);
        ((uint4*)a.dst)[idx] = u;
    }
}

// =====================================================================
// GEMM: cp.async 3-stage pipeline + ldmatrix with register fragment
// double-buffering. CTA 256x128, 8 warps (4m x 2n), warp 64x64, BK=32.
// mode 0: fp32 out[m*1024+n]
// mode 1: tf32 bits out in [B,H,L,DK]
// mode 2: tf32 bits out in [B,H,DK,L]  (direct V transpose)
// =====================================================================
constexpr int AW = 256 * 32;
constexpr int BW = 128 * 32;
constexpr int STAGE_W = AW + BW;
constexpr int GEMM_SMEM_BYTES = 3 * STAGE_W * 4;  // 147456

__device__ __forceinline__ void gemm_core(const float* __restrict__ X,
                                          const float* __restrict__ W,
                                          const float* __restrict__ bias,
                                          float* __restrict__ out,
                                          int mode, int bx, int by,
                                          uint32_t sbase)
{
    const int tid  = threadIdx.x;
    const int w    = tid >> 5;
    const int lane = tid & 31;
    const int gid  = lane >> 2;
    const int t4   = lane & 3;

    const int m0 = by * 256;
    const int n0 = bx * 128;
    const int wm = (w >> 1) * 64;
    const int wn = (w & 1) * 64;

    const int lr = tid >> 3;
    const int ch = tid & 7;

    const int within = lane & 7;
    const int sel    = lane >> 3;

    float acc[4][8][4] = {};

    auto issue = [&](int stage, int kt) {
        const uint32_t ab = sbase + stage * (STAGE_W * 4);
        const uint32_t bb = ab + AW * 4;
        const float* ap = X + (size_t)(m0 + lr) * Dd + kt * 32 + ch * 4;
        #pragma unroll
        for (int i = 0; i < 8; i++) {
            const int row = lr + 32 * i;
            const uint32_t dst = ab + row * 128 + ((ch ^ (row & 7)) << 4);
            CP16(dst, ap + (size_t)(32 * i) * Dd);
        }
        const float* bp = W + (size_t)(n0 + lr) * Dd + kt * 32 + ch * 4;
        #pragma unroll
        for (int i = 0; i < 4; i++) {
            const int row = lr + 32 * i;
            const uint32_t dst = bb + row * 128 + ((ch ^ (row & 7)) << 4);
            CP16(dst, bp + (size_t)(32 * i) * Dd);
        }
        CP_COMMIT();
    };

    issue(0, 0);
    issue(1, 1);

    uint32_t af[2][4][4], bf[2][4][4];

    for (int kt = 0; kt < 32; kt++) {
        const int cs = kt % 3;
        CP_WAIT1();
        __syncthreads();
        if (kt < 30) issue((kt + 2) % 3, kt + 2);
        else         CP_COMMIT();

        const uint32_t ab = sbase + cs * (STAGE_W * 4);
        const uint32_t bb = ab + AW * 4;

        // fragment loader for k-group g into buffer slot
        auto ldfrag = [&](int g, int slot) {
            #pragma unroll
            for (int tm = 0; tm < 4; tm++) {
                const int row = wm + tm * 16 + ((sel & 1) << 3) + within;
                const int cc  = 2 * g + (sel >> 1);
                ldsm4(af[slot][tm], ab + row * 128 + ((cc ^ (row & 7)) << 4));
            }
            #pragma unroll
            for (int np = 0; np < 4; np++) {
                const int row = wn + (2 * np + (sel >> 1)) * 8 + within;
                const int cc  = 2 * g + (sel & 1);
                ldsm4(bf[slot][np], bb + row * 128 + ((cc ^ (row & 7)) << 4));
            }
        };

        ldfrag(0, 0);
        #pragma unroll
        for (int g = 0; g < 4; g++) {
            const int cur = g & 1;
            if (g < 3) ldfrag(g + 1, cur ^ 1);
            #pragma unroll
            for (int tm = 0; tm < 4; tm++)
                #pragma unroll
                for (int np = 0; np < 4; np++) {
                    mma_tf32(acc[tm][2 * np],     af[cur][tm], &bf[cur][np][0]);
                    mma_tf32(acc[tm][2 * np + 1], af[cur][tm], &bf[cur][np][2]);
                }
        }
    }

    #pragma unroll
    for (int tm = 0; tm < 4; tm++) {
        const int r0 = m0 + wm + tm * 16 + gid;
        const int r1 = r0 + 8;
        #pragma unroll
        for (int tn = 0; tn < 8; tn++) {
            const int cc = n0 + wn + tn * 8 + t4 * 2;
            const float bv0 = __ldg(bias + cc);
            const float bv1 = __ldg(bias + cc + 1);
            float2 v0, v1;
            v0.x = acc[tm][tn][0] + bv0;  v0.y = acc[tm][tn][1] + bv1;
            v1.x = acc[tm][tn][2] + bv0;  v1.y = acc[tm][tn][3] + bv1;
            if (mode == 0) {
                *(float2*)(out + (size_t)r0 * Dd + cc) = v0;
                *(float2*)(out + (size_t)r1 * Dd + cc) = v1;
            } else if (mode == 1) {
                v0.x = __uint_as_float(f2tf32(v0.x));
                v0.y = __uint_as_float(f2tf32(v0.y));
                v1.x = __uint_as_float(f2tf32(v1.x));
                v1.y = __uint_as_float(f2tf32(v1.y));
                const int h = cc >> 6, dk = cc & 63;
                {
                    const int b = r0 >> 11, l = r0 & 2047;
                    *(float2*)(out + (((size_t)(b * Hh + h) * Lc + l) << 6) + dk) = v0;
                }
                {
                    const int b = r1 >> 11, l = r1 & 2047;
                    *(float2*)(out + (((size_t)(b * Hh + h) * Lc + l) << 6) + dk) = v1;
                }
            } else {   // mode 2: V -> [B,H,DK,L]
                const int h = cc >> 6, dk = cc & 63;
                {
                    const int b = r0 >> 11, l = r0 & 2047;
                    float* vb = out + ((size_t)(b * Hh + h) * DK + dk) * Lc;
                    vb[l]      = __uint_as_float(f2tf32(v0.x));
                    vb[Lc + l] = __uint_as_float(f2tf32(v0.y));
                }
                {
                    const int b = r1 >> 11, l = r1 & 2047;
                    float* vb = out + ((size_t)(b * Hh + h) * DK + dk) * Lc;
                    vb[l]      = __uint_as_float(f2tf32(v1.x));
                    vb[Lc + l] = __uint_as_float(f2tf32(v1.y));
                }
            }
        }
    }
}

struct QKVArgs {
    const float* X[3];
    const float* W[3];
    const float* bias[3];
    float* out[3];
};

__global__ void __launch_bounds__(256) gemm_qkv_kernel(QKVArgs args)
{
    extern __shared__ uint32_t sg[];
    const int z = blockIdx.z;
    gemm_core(args.X[z], args.W[z], args.bias[z], args.out[z],
              (z == 2) ? 2 : 1, blockIdx.x, blockIdx.y, smem_u32(sg));
}

__global__ void __launch_bounds__(256) gemm_o_kernel(const float* __restrict__ X,
                                                     const float* __restrict__ W,
                                                     const float* __restrict__ bias,
                                                     float* __restrict__ out)
{
    extern __shared__ uint32_t sg[];
    gemm_core(X, W, bias, out, 0, blockIdx.x, blockIdx.y, smem_u32(sg));
}

// =====================================================================
// Causal flash attention: 64-key tiles, cp.async 3-stage + ldmatrix.
// CTA: 128 q-rows, 8 warps; warp = 16 q x 64 keys.
// Batched ldsm per chunk ahead of mmas.
// =====================================================================
constexpr int ATT_KW = 64 * 64;
constexpr int ATT_VW = 64 * 64;
constexpr int ATT_STAGE_W = ATT_KW + ATT_VW;          // 8192 words
constexpr int ATTN_SMEM_BYTES = 3 * ATT_STAGE_W * 4;  // 98304

__global__ void __launch_bounds__(256, 2) attn_mma_kernel(const float* __restrict__ Qg,
                                                          const float* __restrict__ Kg,
                                                          const float* __restrict__ Vtg,
                                                          float* __restrict__ att)
{
    extern __shared__ uint32_t sa[];
    const uint32_t sb = smem_u32(sa);

    const int tid  = threadIdx.x;
    const int w    = tid >> 5;
    const int lane = tid & 31;
    const int gid  = lane >> 2;
    const int t4   = lane & 3;
    const int within = lane & 7;
    const int sel    = lane >> 3;

    const int qb = gridDim.x - 1 - blockIdx.x;   // LPT
    const int q0 = qb * 128;
    const int h  = blockIdx.y;
    const int b  = blockIdx.z;

    const int wq    = q0 + w * 16;
    const int qrow0 = wq + gid;

    const size_t base = (size_t)(b * Hh + h) * Lc * DK;
    const float* Qbh  = Qg + base;
    const float* Kbh  = Kg + base;
    const float* Vtbh = Vtg + base;   // [DK][L]

    // ---- Q fragments (tf32 bits; *0.125 exact) ----
    uint32_t qf[8][4];
    {
        const float* qp0 = Qbh + (size_t)qrow0 * DK;
        const float* qp1 = qp0 + 8 * DK;
        #pragma unroll
        for (int kc = 0; kc < 8; kc++) {
            const int c0 = kc * 8 + t4, c1 = c0 + 4;
            qf[kc][0] = __float_as_uint(__ldg(qp0 + c0) * 0.125f);
            qf[kc][1] = __float_as_uint(__ldg(qp1 + c0) * 0.125f);
            qf[kc][2] = __float_as_uint(__ldg(qp0 + c1) * 0.125f);
            qf[kc][3] = __float_as_uint(__ldg(qp1 + c1) * 0.125f);
        }
    }

    float Oacc[8][4] = {};
    float mrow0 = -3.0e38f, mrow1 = -3.0e38f;
    float lrow0 = 0.0f,     lrow1 = 0.0f;

    auto issueKV = [&](int stage, int k0) {
        const uint32_t kb = sb + stage * (ATT_STAGE_W * 4);
        const uint32_t vb = kb + ATT_KW * 4;
        #pragma unroll
        for (int i = 0; i < 4; i++) {
            const int idx = tid + i * 256;
            const int row = idx >> 4, c = idx & 15;
            CP16(kb + row * 256 + ((c ^ (row & 7)) << 4),
                 Kbh + (size_t)(k0 + row) * DK + c * 4);
            CP16(vb + row * 256 + ((c ^ (row & 7)) << 4),
                 Vtbh + (size_t)row * Lc + k0 + c * 4);
        }
        CP_COMMIT();
    };

    const int ntiles = q0 / 64 + 2;
    issueKV(0, 0);
    issueKV(1, 64);

    const int src0 = (lane & ~3) + (t4 >> 1);
    const int src2 = src0 + 2;
    const bool odd = (t4 & 1) != 0;

    for (int t = 0; t < ntiles; t++) {
        const int k0 = t * 64;
        const int cs = t % 3;
        CP_WAIT1();
        __syncthreads();
        if (t + 2 < ntiles) issueKV((t + 2) % 3, (t + 2) * 64);
        else                CP_COMMIT();

        if (k0 <= wq + 15) {
            const uint32_t kst = sb + cs * (ATT_STAGE_W * 4);
            const uint32_t vst = kst + ATT_KW * 4;

            // ---- S = Q' K^T (16q x 64k): batch 4 ldsm, then 8 mma ----
            float s[8][4] = {};
            #pragma unroll
            for (int st8 = 0; st8 < 8; st8++) {
                uint32_t bf[4][4];
                #pragma unroll
                for (int np = 0; np < 4; np++) {
                    const int row = (2 * np + (sel >> 1)) * 8 + within;
                    const int cc  = 2 * st8 + (sel & 1);
                    ldsm4(bf[np], kst + row * 256 + ((cc ^ (row & 7)) << 4));
                }
                #pragma unroll
                for (int np = 0; np < 4; np++) {
                    mma_tf32(s[2 * np],     qf[st8], &bf[np][0]);
                    mma_tf32(s[2 * np + 1], qf[st8], &bf[np][2]);
                }
            }
            // ---- causal mask (diagonal tiles only) ----
            if (k0 + 63 > wq) {
                #pragma unroll
                for (int tn = 0; tn < 8; tn++) {
                    const int c = k0 + tn * 8 + 2 * t4;
                    if (c     > qrow0)     s[tn][0] = -3.0e38f;
                    if (c + 1 > qrow0)     s[tn][1] = -3.0e38f;
                    if (c     > qrow0 + 8) s[tn][2] = -3.0e38f;
                    if (c + 1 > qrow0 + 8) s[tn][3] = -3.0e38f;
                }
            }
            // ---- register softmax ----
            float mx0 = s[0][0], mx1 = s[0][2];
            #pragma unroll
            for (int tn = 0; tn < 8; tn++) {
                mx0 = fmaxf(mx0, fmaxf(s[tn][0], s[tn][1]));
                mx1 = fmaxf(mx1, fmaxf(s[tn][2], s[tn][3]));
            }
            mx0 = fmaxf(mx0, __shfl_xor_sync(0xffffffffu, mx0, 1));
            mx0 = fmaxf(mx0, __shfl_xor_sync(0xffffffffu, mx0, 2));
            mx1 = fmaxf(mx1, __shfl_xor_sync(0xffffffffu, mx1, 1));
            mx1 = fmaxf(mx1, __shfl_xor_sync(0xffffffffu, mx1, 2));
            const float mn0 = fmaxf(mrow0, mx0);
            const float mn1 = fmaxf(mrow1, mx1);

            float ps0 = 0.0f, ps1 = 0.0f;
            #pragma unroll
            for (int tn = 0; tn < 8; tn++) {
                float p0 = __expf(s[tn][0] - mn0);
                float p1 = __expf(s[tn][1] - mn0);
                float p2 = __expf(s[tn][2] - mn1);
                float p3 = __expf(s[tn][3] - mn1);
                ps0 += p0 + p1;
                ps1 += p2 + p3;
                s[tn][0] = p0; s[tn][1] = p1; s[tn][2] = p2; s[tn][3] = p3;
            }
            ps0 += __shfl_xor_sync(0xffffffffu, ps0, 1);
            ps0 += __shfl_xor_sync(0xffffffffu, ps0, 2);
            ps1 += __shfl_xor_sync(0xffffffffu, ps1, 1);
            ps1 += __shfl_xor_sync(0xffffffffu, ps1, 2);

            const float al0 = __expf(mrow0 - mn0);
            const float al1 = __expf(mrow1 - mn1);
            lrow0 = lrow0 * al0 + ps0;
            lrow1 = lrow1 * al1 + ps1;
            mrow0 = mn0;
            mrow1 = mn1;
            #pragma unroll
            for (int nd = 0; nd < 8; nd++) {
                Oacc[nd][0] *= al0; Oacc[nd][1] *= al0;
                Oacc[nd][2] *= al1; Oacc[nd][3] *= al1;
            }

            // ---- per 8-key chunk: shuffle P + batched vf ldsm, then mmas ----
            #pragma unroll
            for (int g = 0; g < 8; g++) {
                uint32_t vf[4][4];
                #pragma unroll
                for (int np = 0; np < 4; np++) {
                    const int row = (2 * np + (sel >> 1)) * 8 + within;
                    const int cc  = 2 * g + (sel & 1);
                    ldsm4(vf[np], vst + row * 256 + ((cc ^ (row & 7)) << 4));
                }
                float f00 = __shfl_sync(0xffffffffu, s[g][0], src0);
                float f01 = __shfl_sync(0xffffffffu, s[g][1], src0);
                float f10 = __shfl_sync(0xffffffffu, s[g][2], src0);
                float f11 = __shfl_sync(0xffffffffu, s[g][3], src0);
                float f20 = __shfl_sync(0xffffffffu, s[g][0], src2);
                float f21 = __shfl_sync(0xffffffffu, s[g][1], src2);
                float f30 = __shfl_sync(0xffffffffu, s[g][2], src2);
                float f31 = __shfl_sync(0xffffffffu, s[g][3], src2);
                uint32_t pa[4];
                pa[0] = f2tf32(odd ? f01 : f00);
                pa[1] = f2tf32(odd ? f11 : f10);
                pa[2] = f2tf32(odd ? f21 : f20);
                pa[3] = f2tf32(odd ? f31 : f30);
                #pragma unroll
                for (int np = 0; np < 4; np++) {
                    mma_tf32(Oacc[2 * np],     pa, &vf[np][0]);
                    mma_tf32(Oacc[2 * np + 1], pa, &vf[np][2]);
                }
            }
        }
    }

    // ---- write normalized output (tf32 bits) to [B,L,D] ----
    const float inv0 = 1.0f / lrow0;
    const float inv1 = 1.0f / lrow1;
    float* o0 = att + ((size_t)(b * Lc + qrow0))     * Dd + h * DK;
    float* o1 = att + ((size_t)(b * Lc + qrow0 + 8)) * Dd + h * DK;
    #pragma unroll
    for (int nd = 0; nd < 8; nd++) {
        const int cc = nd * 8 + 2 * t4;
        float2 v0, v1;
        v0.x = __uint_as_float(f2tf32(Oacc[nd][0] * inv0));
        v0.y = __uint_as_float(f2tf32(Oacc[nd][1] * inv0));
        v1.x = __uint_as_float(f2tf32(Oacc[nd][2] * inv1));
        v1.y = __uint_as_float(f2tf32(Oacc[nd][3] * inv1));
        *(float2*)(o0 + cc) = v0;
        *(float2*)(o1 + cc) = v1;
    }
}

// ---------------- launch ----------------
extern "C" void kernel_launch(void* const* d_in, const int* in_sizes, int n_in,
                              void* d_out, int out_size)
{
    const float* q    = (const float*)d_in[0];
    const float* k    = (const float*)d_in[1];
    const float* v    = (const float*)d_in[2];
    const float* wq_w = (const float*)d_in[3];
    const float* wq_b = (const float*)d_in[4];
    const float* wk_w = (const float*)d_in[5];
    const float* wk_b = (const float*)d_in[6];
    const float* wv_w = (const float*)d_in[7];
    const float* wv_b = (const float*)d_in[8];
    const float* wo_w = (const float*)d_in[9];
    const float* wo_b = (const float*)d_in[10];
    float* out = (float*)d_out;

    float *pQ, *pK, *pVt, *pAtt, *pConv;
    cudaGetSymbolAddress((void**)&pQ,    g_Q);
    cudaGetSymbolAddress((void**)&pK,    g_K);
    cudaGetSymbolAddress((void**)&pVt,   g_Vt);
    cudaGetSymbolAddress((void**)&pAtt,  g_att);
    cudaGetSymbolAddress((void**)&pConv, g_conv);

    cudaFuncSetAttribute(gemm_qkv_kernel, cudaFuncAttributeMaxDynamicSharedMemorySize, GEMM_SMEM_BYTES);
    cudaFuncSetAttribute(gemm_o_kernel,   cudaFuncAttributeMaxDynamicSharedMemorySize, GEMM_SMEM_BYTES);
    cudaFuncSetAttribute(attn_mma_kernel, cudaFuncAttributeMaxDynamicSharedMemorySize, ATTN_SMEM_BYTES);

    // ---- fused tf32 pre-convert ----
    ConvArgs ca;
    ca.s0 = (const float4*)q;    ca.s1 = (const float4*)k;    ca.s2 = (const float4*)v;
    ca.s3 = (const float4*)wq_w; ca.s4 = (const float4*)wk_w; ca.s5 = (const float4*)wv_w;
    ca.s6 = (const float4*)wo_w;
    ca.dst = (float4*)pConv;
    conv_all_kernel<<<SEG_TOT / 4 / 256, 256>>>(ca);

    const float* pqc = pConv + (size_t)SEG_Q  * 4;
    const float* pkc = pConv + (size_t)SEG_K  * 4;
    const float* pvc = pConv + (size_t)SEG_V  * 4;
    const float* pwq = pConv + (size_t)SEG_WQ * 4;
    const float* pwk = pConv + (size_t)SEG_WK * 4;
    const float* pwv = pConv + (size_t)SEG_WV * 4;
    const float* pwo = pConv + (size_t)SEG_WO * 4;

    QKVArgs args;
    args.X[0] = pqc;  args.X[1] = pkc;  args.X[2] = pvc;
    args.W[0] = pwq;  args.W[1] = pwk;  args.W[2] = pwv;
    args.bias[0] = wq_b; args.bias[1] = wk_b; args.bias[2] = wv_b;
    args.out[0] = pQ; args.out[1] = pK; args.out[2] = pVt;

    dim3 gq(Dd / 128, Mtok / 256, 3);   // (8, 32, 3)
    gemm_qkv_kernel<<<gq, 256, GEMM_SMEM_BYTES>>>(args);

    dim3 ga(Lc / 128, Hh, Bc);          // (16, 16, 4)
    attn_mma_kernel<<<ga, 256, ATTN_SMEM_BYTES>>>(pQ, pK, pVt, pAtt);

    dim3 gg(Dd / 128, Mtok / 256);      // (8, 32)
    gemm_o_kernel<<<gg, 256, GEMM_SMEM_BYTES>>>(pAtt, pwo, wo_b, out);
}

// round 14
// speedup vs baseline: 1.8477x; 1.8477x over previous
#include <cuda_runtime.h>
#include <cuda_fp16.h>
#include <math.h>
#include <cstdint>

constexpr int Bc = 4;
constexpr int Lc = 2048;
constexpr int Dd = 1024;
constexpr int Hh = 16;
constexpr int DK = 64;
constexpr int Mtok = Bc * Lc;   // 8192

// ---------------- scratch (halves) ----------------
__device__ __half g_Q[Bc * Hh * Lc * DK];   // [B,H,L,DK]
__device__ __half g_K[Bc * Hh * Lc * DK];
__device__ __half g_Vt[Bc * Hh * DK * Lc];  // [B,H,DK,L]
__device__ __half g_att[Bc * Lc * Dd];      // [B,L,D]
__device__ __half g_conv[7340032 * 4];      // concatenated fp16 copies

// segment offsets in float4 (=4-element) units
constexpr int SEG_Q  = 0;
constexpr int SEG_K  = 2097152;
constexpr int SEG_V  = 4194304;
constexpr int SEG_WQ = 6291456;
constexpr int SEG_WK = 6553600;
constexpr int SEG_WV = 6815744;
constexpr int SEG_WO = 7077888;
constexpr int SEG_TOT = 7340032;

// ---------------- helpers ----------------
__device__ __forceinline__ void mma_f16(float* d, const uint32_t* a, const uint32_t* b) {
    asm volatile(
        "mma.sync.aligned.m16n8k16.row.col.f32.f16.f16.f32 "
        "{%0,%1,%2,%3}, {%4,%5,%6,%7}, {%8,%9}, {%0,%1,%2,%3};\n"
        : "+f"(d[0]), "+f"(d[1]), "+f"(d[2]), "+f"(d[3])
        : "r"(a[0]), "r"(a[1]), "r"(a[2]), "r"(a[3]), "r"(b[0]), "r"(b[1]));
}

__device__ __forceinline__ void ldsm4(uint32_t* r, uint32_t addr) {
    asm volatile("ldmatrix.sync.aligned.m8n8.x4.shared.b16 {%0,%1,%2,%3}, [%4];"
                 : "=r"(r[0]), "=r"(r[1]), "=r"(r[2]), "=r"(r[3]) : "r"(addr));
}

__device__ __forceinline__ uint32_t smem_u32(const void* p) {
    uint32_t a;
    asm("{ .reg .u64 t; cvta.to.shared.u64 t, %1; cvt.u32.u64 %0, t; }" : "=r"(a) : "l"(p));
    return a;
}

__device__ __forceinline__ uint32_t packh2(float a, float b) {
    __half2 h = __floats2half2_rn(a, b);
    return *(uint32_t*)&h;
}

#define CP16(dst, src) \
    asm volatile("cp.async.cg.shared.global [%0], [%1], 16;" :: "r"(dst), "l"(src))
#define CP_COMMIT() asm volatile("cp.async.commit_group;")
#define CP_WAIT1()  asm volatile("cp.async.wait_group 1;")

// ---------------- fused fp16 pre-convert (all 7 tensors) ----------------
struct ConvArgs {
    const float4* s0; const float4* s1; const float4* s2;
    const float4* s3; const float4* s4; const float4* s5; const float4* s6;
    __half* dst;
};

__global__ void __launch_bounds__(256) conv_all_kernel(ConvArgs a)
{
    const int g = blockIdx.x * 256 + threadIdx.x;
    constexpr int NT = SEG_TOT / 4;
    #pragma unroll
    for (int p = 0; p < 4; p++) {
        const int idx = g + p * NT;
        float4 v;
        if (idx < SEG_WQ) {
            const int seg = idx >> 21;
            const int off = idx & 2097151;
            v = (seg == 0) ? a.s0[off] : (seg == 1) ? a.s1[off] : a.s2[off];
        } else {
            const int r = idx - SEG_WQ;
            const int seg = r >> 18;
            const int off = r & 262143;
            v = (seg == 0) ? a.s3[off] : (seg == 1) ? a.s4[off]
              : (seg == 2) ? a.s5[off] : a.s6[off];
        }
        uint2 u;
        u.x = packh2(v.x, v.y);
        u.y = packh2(v.z, v.w);
        ((uint2*)a.dst)[idx] = u;
    }
}

// =====================================================================
// GEMM: cp.async 3-stage + ldmatrix, fp16 m16n8k16.
// CTA 256x128, 8 warps (4m x 2n), warp 64x64, BK=64 halves (128B rows).
// mode 0: fp32 out[m*1024+n]
// mode 1: fp16 out in [B,H,L,DK]
// mode 2: fp16 out in [B,H,DK,L]  (direct V transpose)
// =====================================================================
constexpr int ABYTES = 256 * 128;        // A stage bytes
constexpr int BBYTES = 128 * 128;
constexpr int STAGE_B = ABYTES + BBYTES; // 49152
constexpr int GEMM_SMEM_BYTES = 3 * STAGE_B;  // 147456

__device__ __forceinline__ void gemm_core(const __half* __restrict__ X,
                                          const __half* __restrict__ W,
                                          const float* __restrict__ bias,
                                          void* __restrict__ outv,
                                          int mode, int bx, int by,
                                          uint32_t sbase)
{
    const int tid  = threadIdx.x;
    const int w    = tid >> 5;
    const int lane = tid & 31;
    const int gid  = lane >> 2;
    const int t4   = lane & 3;

    const int m0 = by * 256;
    const int n0 = bx * 128;
    const int wm = (w >> 1) * 64;
    const int wn = (w & 1) * 64;

    const int lr = tid >> 3;
    const int ch = tid & 7;

    const int within = lane & 7;
    const int sel    = lane >> 3;

    float acc[4][8][4] = {};

    auto issue = [&](int stage, int kt) {
        const uint32_t ab = sbase + stage * STAGE_B;
        const uint32_t bb = ab + ABYTES;
        const __half* ap = X + (size_t)(m0 + lr) * Dd + kt * 64 + ch * 8;
        #pragma unroll
        for (int i = 0; i < 8; i++) {
            const int row = lr + 32 * i;
            const uint32_t dst = ab + row * 128 + ((ch ^ (row & 7)) << 4);
            CP16(dst, ap + (size_t)(32 * i) * Dd);
        }
        const __half* bp = W + (size_t)(n0 + lr) * Dd + kt * 64 + ch * 8;
        #pragma unroll
        for (int i = 0; i < 4; i++) {
            const int row = lr + 32 * i;
            const uint32_t dst = bb + row * 128 + ((ch ^ (row & 7)) << 4);
            CP16(dst, bp + (size_t)(32 * i) * Dd);
        }
        CP_COMMIT();
    };

    issue(0, 0);
    issue(1, 1);

    for (int kt = 0; kt < 16; kt++) {
        const int cs = kt % 3;
        CP_WAIT1();
        __syncthreads();
        if (kt < 14) issue((kt + 2) % 3, kt + 2);
        else         CP_COMMIT();

        const uint32_t ab = sbase + cs * STAGE_B;
        const uint32_t bb = ab + ABYTES;

        #pragma unroll
        for (int g = 0; g < 4; g++) {     // k-groups of 16
            uint32_t af[4][4];
            #pragma unroll
            for (int tm = 0; tm < 4; tm++) {
                const int row = wm + tm * 16 + ((sel & 1) << 3) + within;
                const int cc  = 2 * g + (sel >> 1);
                ldsm4(af[tm], ab + row * 128 + ((cc ^ (row & 7)) << 4));
            }
            uint32_t bf[4][4];
            #pragma unroll
            for (int np = 0; np < 4; np++) {
                const int row = wn + (2 * np + (sel >> 1)) * 8 + within;
                const int cc  = 2 * g + (sel & 1);
                ldsm4(bf[np], bb + row * 128 + ((cc ^ (row & 7)) << 4));
            }
            #pragma unroll
            for (int tm = 0; tm < 4; tm++)
                #pragma unroll
                for (int np = 0; np < 4; np++) {
                    mma_f16(acc[tm][2 * np],     af[tm], &bf[np][0]);
                    mma_f16(acc[tm][2 * np + 1], af[tm], &bf[np][2]);
                }
        }
    }

    float* outf = (float*)outv;
    __half* outh = (__half*)outv;

    #pragma unroll
    for (int tm = 0; tm < 4; tm++) {
        const int r0 = m0 + wm + tm * 16 + gid;
        const int r1 = r0 + 8;
        #pragma unroll
        for (int tn = 0; tn < 8; tn++) {
            const int cc = n0 + wn + tn * 8 + t4 * 2;
            const float bv0 = __ldg(bias + cc);
            const float bv1 = __ldg(bias + cc + 1);
            float2 v0, v1;
            v0.x = acc[tm][tn][0] + bv0;  v0.y = acc[tm][tn][1] + bv1;
            v1.x = acc[tm][tn][2] + bv0;  v1.y = acc[tm][tn][3] + bv1;
            if (mode == 0) {
                *(float2*)(outf + (size_t)r0 * Dd + cc) = v0;
                *(float2*)(outf + (size_t)r1 * Dd + cc) = v1;
            } else if (mode == 1) {
                const int h = cc >> 6, dk = cc & 63;
                {
                    const int b = r0 >> 11, l = r0 & 2047;
                    *(uint32_t*)(outh + (((size_t)(b * Hh + h) * Lc + l) << 6) + dk)
                        = packh2(v0.x, v0.y);
                }
                {
                    const int b = r1 >> 11, l = r1 & 2047;
                    *(uint32_t*)(outh + (((size_t)(b * Hh + h) * Lc + l) << 6) + dk)
                        = packh2(v1.x, v1.y);
                }
            } else {   // mode 2: V -> [B,H,DK,L]
                const int h = cc >> 6, dk = cc & 63;
                {
                    const int b = r0 >> 11, l = r0 & 2047;
                    __half* vb = outh + ((size_t)(b * Hh + h) * DK + dk) * Lc;
                    vb[l]      = __float2half_rn(v0.x);
                    vb[Lc + l] = __float2half_rn(v0.y);
                }
                {
                    const int b = r1 >> 11, l = r1 & 2047;
                    __half* vb = outh + ((size_t)(b * Hh + h) * DK + dk) * Lc;
                    vb[l]      = __float2half_rn(v1.x);
                    vb[Lc + l] = __float2half_rn(v1.y);
                }
            }
        }
    }
}

struct QKVArgs {
    const __half* X[3];
    const __half* W[3];
    const float* bias[3];
    void* out[3];
};

__global__ void __launch_bounds__(256) gemm_qkv_kernel(QKVArgs args)
{
    extern __shared__ uint32_t sg[];
    const int z = blockIdx.z;
    gemm_core(args.X[z], args.W[z], args.bias[z], args.out[z],
              (z == 2) ? 2 : 1, blockIdx.x, blockIdx.y, smem_u32(sg));
}

__global__ void __launch_bounds__(256) gemm_o_kernel(const __half* __restrict__ X,
                                                     const __half* __restrict__ W,
                                                     const float* __restrict__ bias,
                                                     float* __restrict__ out)
{
    extern __shared__ uint32_t sg[];
    gemm_core(X, W, bias, out, 0, blockIdx.x, blockIdx.y, smem_u32(sg));
}

// =====================================================================
// Causal flash attention, fp16 m16n8k16, shuffle-free P->A conversion.
// CTA: 128 q-rows, 8 warps; warp = 16 q x 64 keys.
// Stage: K 64x128B + Vt 64x128B = 16KB; 3 stages = 48KB.
// =====================================================================
constexpr int ATT_KB = 64 * 128;
constexpr int ATT_VB = 64 * 128;
constexpr int ATT_STAGE_B = ATT_KB + ATT_VB;          // 16384
constexpr int ATTN_SMEM_BYTES = 3 * ATT_STAGE_B;      // 49152

__global__ void __launch_bounds__(256, 2) attn_mma_kernel(const __half* __restrict__ Qg,
                                                          const __half* __restrict__ Kg,
                                                          const __half* __restrict__ Vtg,
                                                          __half* __restrict__ att)
{
    extern __shared__ uint32_t sa[];
    const uint32_t sb = smem_u32(sa);

    const int tid  = threadIdx.x;
    const int w    = tid >> 5;
    const int lane = tid & 31;
    const int gid  = lane >> 2;
    const int t4   = lane & 3;
    const int within = lane & 7;
    const int sel    = lane >> 3;

    const int qb = gridDim.x - 1 - blockIdx.x;   // LPT
    const int q0 = qb * 128;
    const int h  = blockIdx.y;
    const int b  = blockIdx.z;

    const int wq    = q0 + w * 16;
    const int qrow0 = wq + gid;

    const size_t base = (size_t)(b * Hh + h) * Lc * DK;
    const __half* Qbh  = Qg + base;
    const __half* Kbh  = Kg + base;
    const __half* Vtbh = Vtg + base;   // [DK][L]

    // ---- Q fragments: 4 k-groups of 16, half2 packed, pre-scaled ----
    uint32_t qf[4][4];
    {
        const __half2 qs = __float2half2_rn(0.125f);
        const __half* qp0 = Qbh + (size_t)qrow0 * DK;
        const __half* qp1 = qp0 + 8 * DK;
        #pragma unroll
        for (int kc = 0; kc < 4; kc++) {
            const int c0 = kc * 16 + 2 * t4;
            const int c1 = c0 + 8;
            __half2 a0 = __hmul2(*(const __half2*)(qp0 + c0), qs);
            __half2 a1 = __hmul2(*(const __half2*)(qp1 + c0), qs);
            __half2 a2 = __hmul2(*(const __half2*)(qp0 + c1), qs);
            __half2 a3 = __hmul2(*(const __half2*)(qp1 + c1), qs);
            qf[kc][0] = *(uint32_t*)&a0;
            qf[kc][1] = *(uint32_t*)&a1;
            qf[kc][2] = *(uint32_t*)&a2;
            qf[kc][3] = *(uint32_t*)&a3;
        }
    }

    float Oacc[8][4] = {};
    float mrow0 = -3.0e38f, mrow1 = -3.0e38f;
    float lrow0 = 0.0f,     lrow1 = 0.0f;

    auto issueKV = [&](int stage, int k0) {
        const uint32_t kb = sb + stage * ATT_STAGE_B;
        const uint32_t vb = kb + ATT_KB;
        #pragma unroll
        for (int i = 0; i < 2; i++) {
            const int idx = tid + i * 256;           // 0..511
            const int row = idx >> 3, c = idx & 7;
            CP16(kb + row * 128 + ((c ^ (row & 7)) << 4),
                 Kbh + (size_t)(k0 + row) * DK + c * 8);
            CP16(vb + row * 128 + ((c ^ (row & 7)) << 4),
                 Vtbh + (size_t)row * Lc + k0 + c * 8);
        }
        CP_COMMIT();
    };

    const int ntiles = q0 / 64 + 2;
    issueKV(0, 0);
    issueKV(1, 64);

    for (int t = 0; t < ntiles; t++) {
        const int k0 = t * 64;
        const int cs = t % 3;
        CP_WAIT1();
        __syncthreads();
        if (t + 2 < ntiles) issueKV((t + 2) % 3, (t + 2) * 64);
        else                CP_COMMIT();

        if (k0 <= wq + 15) {
            const uint32_t kst = sb + cs * ATT_STAGE_B;
            const uint32_t vst = kst + ATT_KB;

            // ---- S = Q' K^T (16q x 64k): 4 k16-groups ----
            float s[8][4] = {};
            #pragma unroll
            for (int g = 0; g < 4; g++) {
                uint32_t bf[4][4];
                #pragma unroll
                for (int np = 0; np < 4; np++) {
                    const int row = (2 * np + (sel >> 1)) * 8 + within;
                    const int cc  = 2 * g + (sel & 1);
                    ldsm4(bf[np], kst + row * 128 + ((cc ^ (row & 7)) << 4));
                }
                #pragma unroll
                for (int np = 0; np < 4; np++) {
                    mma_f16(s[2 * np],     qf[g], &bf[np][0]);
                    mma_f16(s[2 * np + 1], qf[g], &bf[np][2]);
                }
            }
            // ---- causal mask (diagonal tiles only) ----
            if (k0 + 63 > wq) {
                #pragma unroll
                for (int tn = 0; tn < 8; tn++) {
                    const int c = k0 + tn * 8 + 2 * t4;
                    if (c     > qrow0)     s[tn][0] = -3.0e38f;
                    if (c + 1 > qrow0)     s[tn][1] = -3.0e38f;
                    if (c     > qrow0 + 8) s[tn][2] = -3.0e38f;
                    if (c + 1 > qrow0 + 8) s[tn][3] = -3.0e38f;
                }
            }
            // ---- register softmax ----
            float mx0 = s[0][0], mx1 = s[0][2];
            #pragma unroll
            for (int tn = 0; tn < 8; tn++) {
                mx0 = fmaxf(mx0, fmaxf(s[tn][0], s[tn][1]));
                mx1 = fmaxf(mx1, fmaxf(s[tn][2], s[tn][3]));
            }
            mx0 = fmaxf(mx0, __shfl_xor_sync(0xffffffffu, mx0, 1));
            mx0 = fmaxf(mx0, __shfl_xor_sync(0xffffffffu, mx0, 2));
            mx1 = fmaxf(mx1, __shfl_xor_sync(0xffffffffu, mx1, 1));
            mx1 = fmaxf(mx1, __shfl_xor_sync(0xffffffffu, mx1, 2));
            const float mn0 = fmaxf(mrow0, mx0);
            const float mn1 = fmaxf(mrow1, mx1);

            float ps0 = 0.0f, ps1 = 0.0f;
            #pragma unroll
            for (int tn = 0; tn < 8; tn++) {
                float p0 = __expf(s[tn][0] - mn0);
                float p1 = __expf(s[tn][1] - mn0);
                float p2 = __expf(s[tn][2] - mn1);
                float p3 = __expf(s[tn][3] - mn1);
                ps0 += p0 + p1;
                ps1 += p2 + p3;
                s[tn][0] = p0; s[tn][1] = p1; s[tn][2] = p2; s[tn][3] = p3;
            }
            ps0 += __shfl_xor_sync(0xffffffffu, ps0, 1);
            ps0 += __shfl_xor_sync(0xffffffffu, ps0, 2);
            ps1 += __shfl_xor_sync(0xffffffffu, ps1, 1);
            ps1 += __shfl_xor_sync(0xffffffffu, ps1, 2);

            const float al0 = __expf(mrow0 - mn0);
            const float al1 = __expf(mrow1 - mn1);
            lrow0 = lrow0 * al0 + ps0;
            lrow1 = lrow1 * al1 + ps1;
            mrow0 = mn0;
            mrow1 = mn1;
            #pragma unroll
            for (int nd = 0; nd < 8; nd++) {
                Oacc[nd][0] *= al0; Oacc[nd][1] *= al0;
                Oacc[nd][2] *= al1; Oacc[nd][3] *= al1;
            }

            // ---- O += P V: P C-frag -> A-frag by packing (no shuffles) ----
            #pragma unroll
            for (int g = 0; g < 4; g++) {   // 16-key groups
                uint32_t pa[4];
                pa[0] = packh2(s[2 * g][0],     s[2 * g][1]);
                pa[1] = packh2(s[2 * g][2],     s[2 * g][3]);
                pa[2] = packh2(s[2 * g + 1][0], s[2 * g + 1][1]);
                pa[3] = packh2(s[2 * g + 1][2], s[2 * g + 1][3]);
                uint32_t vf[4][4];
                #pragma unroll
                for (int np = 0; np < 4; np++) {
                    const int row = (2 * np + (sel >> 1)) * 8 + within;
                    const int cc  = 2 * g + (sel & 1);
                    ldsm4(vf[np], vst + row * 128 + ((cc ^ (row & 7)) << 4));
                }
                #pragma unroll
                for (int np = 0; np < 4; np++) {
                    mma_f16(Oacc[2 * np],     pa, &vf[np][0]);
                    mma_f16(Oacc[2 * np + 1], pa, &vf[np][2]);
                }
            }
        }
    }

    // ---- write normalized output (fp16) to [B,L,D] ----
    const float inv0 = 1.0f / lrow0;
    const float inv1 = 1.0f / lrow1;
    __half* o0 = att + ((size_t)(b * Lc + qrow0))     * Dd + h * DK;
    __half* o1 = att + ((size_t)(b * Lc + qrow0 + 8)) * Dd + h * DK;
    #pragma unroll
    for (int nd = 0; nd < 8; nd++) {
        const int cc = nd * 8 + 2 * t4;
        *(uint32_t*)(o0 + cc) = packh2(Oacc[nd][0] * inv0, Oacc[nd][1] * inv0);
        *(uint32_t*)(o1 + cc) = packh2(Oacc[nd][2] * inv1, Oacc[nd][3] * inv1);
    }
}

// ---------------- launch ----------------
extern "C" void kernel_launch(void* const* d_in, const int* in_sizes, int n_in,
                              void* d_out, int out_size)
{
    const float* q    = (const float*)d_in[0];
    const float* k    = (const float*)d_in[1];
    const float* v    = (const float*)d_in[2];
    const float* wq_w = (const float*)d_in[3];
    const float* wq_b = (const float*)d_in[4];
    const float* wk_w = (const float*)d_in[5];
    const float* wk_b = (const float*)d_in[6];
    const float* wv_w = (const float*)d_in[7];
    const float* wv_b = (const float*)d_in[8];
    const float* wo_w = (const float*)d_in[9];
    const float* wo_b = (const float*)d_in[10];
    float* out = (float*)d_out;

    __half *pQ, *pK, *pVt, *pAtt, *pConv;
    cudaGetSymbolAddress((void**)&pQ,    g_Q);
    cudaGetSymbolAddress((void**)&pK,    g_K);
    cudaGetSymbolAddress((void**)&pVt,   g_Vt);
    cudaGetSymbolAddress((void**)&pAtt,  g_att);
    cudaGetSymbolAddress((void**)&pConv, g_conv);

    cudaFuncSetAttribute(gemm_qkv_kernel, cudaFuncAttributeMaxDynamicSharedMemorySize, GEMM_SMEM_BYTES);
    cudaFuncSetAttribute(gemm_o_kernel,   cudaFuncAttributeMaxDynamicSharedMemorySize, GEMM_SMEM_BYTES);
    cudaFuncSetAttribute(attn_mma_kernel, cudaFuncAttributeMaxDynamicSharedMemorySize, ATTN_SMEM_BYTES);

    // ---- fused fp16 pre-convert ----
    ConvArgs ca;
    ca.s0 = (const float4*)q;    ca.s1 = (const float4*)k;    ca.s2 = (const float4*)v;
    ca.s3 = (const float4*)wq_w; ca.s4 = (const float4*)wk_w; ca.s5 = (const float4*)wv_w;
    ca.s6 = (const float4*)wo_w;
    ca.dst = pConv;
    conv_all_kernel<<<SEG_TOT / 4 / 256, 256>>>(ca);

    const __half* pqc = pConv + (size_t)SEG_Q  * 4;
    const __half* pkc = pConv + (size_t)SEG_K  * 4;
    const __half* pvc = pConv + (size_t)SEG_V  * 4;
    const __half* pwq = pConv + (size_t)SEG_WQ * 4;
    const __half* pwk = pConv + (size_t)SEG_WK * 4;
    const __half* pwv = pConv + (size_t)SEG_WV * 4;
    const __half* pwo = pConv + (size_t)SEG_WO * 4;

    QKVArgs args;
    args.X[0] = pqc;  args.X[1] = pkc;  args.X[2] = pvc;
    args.W[0] = pwq;  args.W[1] = pwk;  args.W[2] = pwv;
    args.bias[0] = wq_b; args.bias[1] = wk_b; args.bias[2] = wv_b;
    args.out[0] = pQ; args.out[1] = pK; args.out[2] = pVt;

    dim3 gq(Dd / 128, Mtok / 256, 3);   // (8, 32, 3)
    gemm_qkv_kernel<<<gq, 256, GEMM_SMEM_BYTES>>>(args);

    dim3 ga(Lc / 128, Hh, Bc);          // (16, 16, 4)
    attn_mma_kernel<<<ga, 256, ATTN_SMEM_BYTES>>>(pQ, pK, pVt, pAtt);

    dim3 gg(Dd / 128, Mtok / 256);      // (8, 32)
    gemm_o_kernel<<<gg, 256, GEMM_SMEM_BYTES>>>(pAtt, pwo, wo_b, out);
}